// round 4
// baseline (speedup 1.0000x reference)
#include <cuda_runtime.h>
#include <cstdint>

#define NEGV   (-1e30f)
#define Hdim   768
#define Bn     16
#define CLn    512
#define QLn    64
#define TS     68     // tile stride (64 + 4 pad)
#define SSS    65     // S logits stride (scalar access only)

// Scratch (allocation-free rule: device globals)
__device__ float g_m[Bn * CLn];      // row-max masked logits for b_att
__device__ float g_q2c[Bn * Hdim];   // q2c vectors

// ---- packed f32x2 helpers (Blackwell 2x fp32 FMA path, PTX-only) ----
__device__ __forceinline__ void fma2(unsigned long long& d,
                                     unsigned long long a,
                                     unsigned long long b) {
    asm("fma.rn.f32x2 %0, %1, %2, %0;" : "+l"(d) : "l"(a), "l"(b));
}
__device__ __forceinline__ unsigned long long pack2(float x, float y) {
    unsigned long long r;
    asm("mov.b64 %0, {%1, %2};" : "=l"(r) : "f"(x), "f"(y));
    return r;
}
__device__ __forceinline__ float2 unpack2(unsigned long long v) {
    float2 r;
    asm("mov.b64 {%0, %1}, %2;" : "=f"(r.x), "=f"(r.y) : "l"(v));
    return r;
}

// =====================================================================
// K1: per (batch, 64-row i-tile):
//   S = (c*w_cq) @ q^T + cw_i + qw_j + bias    (64x64, K=768)
//   a = softmax_j(mask(S,qm));  m_i = max_j mask(S,cm)  -> g_m
//   c2q = a @ q   (64x768)
//   writes out chunks 0 (c), 1 (c2q), 2 (c*c2q)
// Static smem only (35.6 KB), no cudaFuncSetAttribute needed.
// =====================================================================
__global__ __launch_bounds__(256)
void k1_attn(const float* __restrict__ c, const float* __restrict__ q,
             const float* __restrict__ c_mask, const float* __restrict__ q_mask,
             const float* __restrict__ w_c, const float* __restrict__ b_c,
             const float* __restrict__ w_q, const float* __restrict__ b_q,
             const float* __restrict__ w_cq, const float* __restrict__ b_cq,
             float* __restrict__ out)
{
    __shared__ float bufA[64 * TS];   // phase1: c*w_cq tile | phase2/3: At[j][i]
    __shared__ float bufB[64 * TS];   // phase1/3: q tile    | between: S logits (stride SSS)
    __shared__ float qm_s[64];
    __shared__ float cw_s[64];
    __shared__ float qw_s[64];

    float* Ss = bufB;                 // alias, stride SSS (scalar access)
    float* At = bufA;                 // alias, stride TS

    const int t    = threadIdx.x;
    const int lane = t & 31;
    const int warp = t >> 5;
    const int tx   = t & 15;          // j-group (phase1) / d-group (phase3)
    const int ty   = t >> 4;          // i-group
    const int b    = blockIdx.x >> 3;
    const int i0   = (blockIdx.x & 7) * 64;

    if (t < 64) qm_s[t] = q_mask[b * QLn + t];

    // ---- row dots: cw[i] = c_i . w_c ; qw[j] = q_j . w_q ----
    {
        const float4* wc4 = (const float4*)w_c;
        const float4* wq4 = (const float4*)w_q;
        for (int task = warp; task < 128; task += 8) {
            const float4* row4;
            const float4* w4;
            if (task < 64) {
                row4 = (const float4*)(c + (size_t)(b * CLn + i0 + task) * Hdim);
                w4 = wc4;
            } else {
                row4 = (const float4*)(q + (size_t)(b * QLn + task - 64) * Hdim);
                w4 = wq4;
            }
            float s = 0.f;
            #pragma unroll
            for (int u = 0; u < 6; ++u) {
                float4 a = row4[lane + 32 * u];
                float4 w = w4[lane + 32 * u];
                s += a.x * w.x + a.y * w.y + a.z * w.z + a.w * w.w;
            }
            #pragma unroll
            for (int o = 16; o; o >>= 1) s += __shfl_xor_sync(0xffffffffu, s, o);
            if (lane == 0) { if (task < 64) cw_s[task] = s; else qw_s[task - 64] = s; }
        }
    }

    // ---- phase 1: S GEMM (K-chunks of 64), f32x2 pairing over K ----
    unsigned long long acc[4][4];
    #pragma unroll
    for (int r = 0; r < 4; ++r)
        #pragma unroll
        for (int rj = 0; rj < 4; ++rj) acc[r][rj] = 0ull;

    const int sw = tx & 3;            // B-tile swizzle key (== (row>>2)&3 for rows tx*4..+3)
    const float4* wcq4 = (const float4*)w_cq;
    for (int kc = 0; kc < 12; ++kc) {
        const float4* c4 = (const float4*)(c + (size_t)(b * CLn + i0) * Hdim + kc * 64);
        const float4* q4 = (const float4*)(q + (size_t)(b * QLn) * Hdim + kc * 64);
        __syncthreads();              // previous iteration done reading tiles
        #pragma unroll
        for (int u = 0; u < 4; ++u) {
            int idx = t + 256 * u;
            int row = idx >> 4, col = idx & 15;
            float4 v = c4[row * 192 + col];
            float4 w = wcq4[kc * 16 + col];
            v.x *= w.x; v.y *= w.y; v.z *= w.z; v.w *= w.w;
            *(float4*)(bufA + row * TS + col * 4) = v;
            // XOR-swizzled store of q tile (kills 8-way load conflicts)
            *(float4*)(bufB + row * TS + ((col ^ ((row >> 2) & 3)) << 2)) = q4[row * 192 + col];
        }
        __syncthreads();
        #pragma unroll 4
        for (int kk = 0; kk < 64; kk += 4) {
            const int gb = (((kk >> 2) ^ sw) << 2);
            ulonglong2 A[4], Bv[4];
            #pragma unroll
            for (int r = 0; r < 4; ++r)
                A[r] = *(const ulonglong2*)(bufA + (ty * 4 + r) * TS + kk);
            #pragma unroll
            for (int rj = 0; rj < 4; ++rj)
                Bv[rj] = *(const ulonglong2*)(bufB + (tx * 4 + rj) * TS + gb);
            #pragma unroll
            for (int r = 0; r < 4; ++r)
                #pragma unroll
                for (int rj = 0; rj < 4; ++rj) {
                    fma2(acc[r][rj], A[r].x, Bv[rj].x);
                    fma2(acc[r][rj], A[r].y, Bv[rj].y);
                }
        }
    }
    __syncthreads();   // tiles dead; bufB becomes S logits

    // ---- finalize S logits into Ss (bufB) ----
    {
        const float bias = b_c[0] + b_q[0] + b_cq[0];
        #pragma unroll
        for (int r = 0; r < 4; ++r) {
            int i = ty * 4 + r;
            float base_i = cw_s[i] + bias;
            #pragma unroll
            for (int rj = 0; rj < 4; ++rj) {
                int j = tx * 4 + rj;
                float2 p = unpack2(acc[r][rj]);
                Ss[i * SSS + j] = p.x + p.y + base_i + qw_s[j];
            }
        }
    }
    __syncthreads();

    // ---- phase 2: softmax rows -> At[j][i] (bufA); masked row max -> g_m ----
    #pragma unroll
    for (int r8 = 0; r8 < 8; ++r8) {
        int i = warp * 8 + r8;
        float v0 = Ss[i * SSS + lane];
        float v1 = Ss[i * SSS + 32 + lane];
        float qm0 = qm_s[lane], qm1 = qm_s[32 + lane];
        float l0 = v0 * qm0 + (1.f - qm0) * NEGV;
        float l1 = v1 * qm1 + (1.f - qm1) * NEGV;
        float mx = fmaxf(l0, l1);
        #pragma unroll
        for (int o = 16; o; o >>= 1) mx = fmaxf(mx, __shfl_xor_sync(0xffffffffu, mx, o));
        float e0 = __expf(l0 - mx), e1 = __expf(l1 - mx);
        float s2 = e0 + e1;
        #pragma unroll
        for (int o = 16; o; o >>= 1) s2 += __shfl_xor_sync(0xffffffffu, s2, o);
        float inv = __fdividef(1.f, s2);
        At[lane * TS + i]        = e0 * inv;     // transposed store: At[j][i]
        At[(32 + lane) * TS + i] = e1 * inv;

        float cmv = c_mask[b * CLn + i0 + i];
        float f0 = v0 * cmv + (1.f - cmv) * NEGV;
        float f1 = v1 * cmv + (1.f - cmv) * NEGV;
        float mm = fmaxf(f0, f1);
        #pragma unroll
        for (int o = 16; o; o >>= 1) mm = fmaxf(mm, __shfl_xor_sync(0xffffffffu, mm, o));
        if (lane == 0) g_m[b * CLn + i0 + i] = mm;
    }

    // ---- phase 3: c2q = a @ q (d-chunks of 64); fused out chunks 0/1/2 ----
    for (int dc = 0; dc < 12; ++dc) {
        const int d0 = dc * 64;
        __syncthreads();              // At written / prior chunk reads done
        const float4* q4 = (const float4*)(q + (size_t)(b * QLn) * Hdim + d0);
        #pragma unroll
        for (int u = 0; u < 4; ++u) {
            int idx = t + 256 * u;
            int row = idx >> 4, col = idx & 15;
            *(float4*)(bufB + row * TS + col * 4) = q4[row * 192 + col];
        }
        __syncthreads();

        unsigned long long a3[4][2];
        #pragma unroll
        for (int r = 0; r < 4; ++r) { a3[r][0] = 0ull; a3[r][1] = 0ull; }

        #pragma unroll 4
        for (int j = 0; j < 64; ++j) {
            float4 av = *(const float4*)(At + j * TS + ty * 4);   // 4 rows' weights
            ulonglong2 qv = *(const ulonglong2*)(bufB + j * TS + tx * 4);
            unsigned long long ad;
            ad = pack2(av.x, av.x); fma2(a3[0][0], ad, qv.x); fma2(a3[0][1], ad, qv.y);
            ad = pack2(av.y, av.y); fma2(a3[1][0], ad, qv.x); fma2(a3[1][1], ad, qv.y);
            ad = pack2(av.z, av.z); fma2(a3[2][0], ad, qv.x); fma2(a3[2][1], ad, qv.y);
            ad = pack2(av.w, av.w); fma2(a3[3][0], ad, qv.x); fma2(a3[3][1], ad, qv.y);
        }

        #pragma unroll
        for (int r = 0; r < 4; ++r) {
            int i = ty * 4 + r;
            float4 cv = *(const float4*)(c + (size_t)(b * CLn + i0 + i) * Hdim + d0 + tx * 4);
            float2 p0 = unpack2(a3[r][0]);
            float2 p1 = unpack2(a3[r][1]);
            float4 t0 = make_float4(p0.x, p0.y, p1.x, p1.y);
            float* ob = out + (size_t)(b * CLn + i0 + i) * 3072 + d0 + tx * 4;
            *(float4*)(ob)        = cv;                                      // chunk 0: c
            *(float4*)(ob + 768)  = t0;                                      // chunk 1: c2q
            *(float4*)(ob + 1536) = make_float4(cv.x * t0.x, cv.y * t0.y,
                                                cv.z * t0.z, cv.w * t0.w);   // chunk 2
        }
    }
}

// =====================================================================
// K2: b_att = softmax_i(g_m[b]); g_q2c[b,d] = sum_i b_att[i]*c[b,i,d]
// grid (16,3), 256 thr; deterministic, no atomics.
// =====================================================================
__global__ __launch_bounds__(256)
void k2_q2c(const float* __restrict__ c)
{
    __shared__ float batt[CLn];
    __shared__ float red[8];
    const int b = blockIdx.x, dc = blockIdx.y;
    const int t = threadIdx.x, lane = t & 31, warp = t >> 5;

    float m0 = g_m[b * CLn + t];
    float m1 = g_m[b * CLn + 256 + t];
    float mx = fmaxf(m0, m1);
    #pragma unroll
    for (int o = 16; o; o >>= 1) mx = fmaxf(mx, __shfl_xor_sync(0xffffffffu, mx, o));
    if (lane == 0) red[warp] = mx;
    __syncthreads();
    float M = red[0];
    #pragma unroll
    for (int w = 1; w < 8; ++w) M = fmaxf(M, red[w]);
    float e0 = __expf(m0 - M), e1 = __expf(m1 - M);
    float s = e0 + e1;
    #pragma unroll
    for (int o = 16; o; o >>= 1) s += __shfl_xor_sync(0xffffffffu, s, o);
    __syncthreads();
    if (lane == 0) red[warp] = s;
    __syncthreads();
    float S = 0.f;
    #pragma unroll
    for (int w = 0; w < 8; ++w) S += red[w];
    float inv = __fdividef(1.f, S);
    batt[t]       = e0 * inv;
    batt[256 + t] = e1 * inv;
    __syncthreads();

    const int col = dc * 256 + t;
    const float* cp = c + (size_t)b * CLn * Hdim + col;
    float a0 = 0.f, a1 = 0.f, a2 = 0.f, a3 = 0.f;
    #pragma unroll 4
    for (int i = 0; i < CLn; i += 4) {
        a0 += batt[i]     * cp[(size_t)i * Hdim];
        a1 += batt[i + 1] * cp[(size_t)(i + 1) * Hdim];
        a2 += batt[i + 2] * cp[(size_t)(i + 2) * Hdim];
        a3 += batt[i + 3] * cp[(size_t)(i + 3) * Hdim];
    }
    g_q2c[b * Hdim + col] = (a0 + a1) + (a2 + a3);
}

// =====================================================================
// K3: output chunk 3 = c * q2c (broadcast over i). Pure streaming.
// =====================================================================
__global__ __launch_bounds__(256)
void k3_mul(const float* __restrict__ c, float* __restrict__ out)
{
    const int f  = blockIdx.x * 256 + threadIdx.x;   // float4 index, 16*512*192 total
    const int d4 = f % 192;
    const int r  = f / 192;          // b*512 + i
    const int b  = r >> 9;
    float4 cv = ((const float4*)c)[f];
    float4 sv = ((const float4*)g_q2c)[b * 192 + d4];
    ((float4*)out)[(size_t)r * 768 + 576 + d4] =
        make_float4(cv.x * sv.x, cv.y * sv.y, cv.z * sv.z, cv.w * sv.w);
}

extern "C" void kernel_launch(void* const* d_in, const int* in_sizes, int n_in,
                              void* d_out, int out_size)
{
    const float* c      = (const float*)d_in[0];
    const float* q      = (const float*)d_in[1];
    const float* c_mask = (const float*)d_in[2];
    const float* q_mask = (const float*)d_in[3];
    const float* w_c    = (const float*)d_in[4];
    const float* b_c    = (const float*)d_in[5];
    const float* w_q    = (const float*)d_in[6];
    const float* b_q    = (const float*)d_in[7];
    const float* w_cq   = (const float*)d_in[8];
    const float* b_cq   = (const float*)d_in[9];
    float* out = (float*)d_out;

    k1_attn<<<128, 256>>>(c, q, c_mask, q_mask, w_c, b_c, w_q, b_q, w_cq, b_cq, out);
    k2_q2c<<<dim3(16, 3), 256>>>(c);
    k3_mul<<<16 * 512 * 192 / 256, 256>>>(c, out);
}

// round 13
// speedup vs baseline: 1.0805x; 1.0805x over previous
#include <cuda_runtime.h>
#include <cstdint>

#define NEGV   (-1e30f)
#define Hdim   768
#define Bn     16
#define CLn    512
#define QLn    64
#define TS     68     // tile stride (64 + 4 pad)
#define SSS    65     // S logits stride (scalar access only)

// Scratch (allocation-free rule: device globals)
__device__ float g_m[Bn * CLn];      // row-max masked logits for b_att
__device__ float g_batt[Bn * CLn];   // softmaxed b_att
__device__ float g_q2c[Bn * Hdim];   // q2c vectors

// ---- packed f32x2 helpers (Blackwell 2x fp32 FMA path, PTX-only) ----
__device__ __forceinline__ void fma2(unsigned long long& d,
                                     unsigned long long a,
                                     unsigned long long b) {
    asm("fma.rn.f32x2 %0, %1, %2, %0;" : "+l"(d) : "l"(a), "l"(b));
}
__device__ __forceinline__ unsigned long long pack2(float x, float y) {
    unsigned long long r;
    asm("mov.b64 %0, {%1, %2};" : "=l"(r) : "f"(x), "f"(y));
    return r;
}
__device__ __forceinline__ float2 unpack2(unsigned long long v) {
    float2 r;
    asm("mov.b64 {%0, %1}, %2;" : "=f"(r.x), "=f"(r.y) : "l"(v));
    return r;
}

// =====================================================================
// K1: per (batch, 64-row i-tile):
//   S = (c*w_cq) @ q^T + cw_i + qw_j + bias    (64x64, K=768)
//   a = softmax_j(mask(S,qm));  m_i = max_j mask(S,cm)  -> g_m
//   c2q = a @ q   (64x768); writes out chunks 0 (c), 1 (c2q), 2 (c*c2q)
// B-tile uses ADDITIVE mod-16 swizzle -> B LDS.128 at 2-wavefront minimum.
// =====================================================================
__global__ __launch_bounds__(256)
void k1_attn(const float* __restrict__ c, const float* __restrict__ q,
             const float* __restrict__ c_mask, const float* __restrict__ q_mask,
             const float* __restrict__ w_c, const float* __restrict__ b_c,
             const float* __restrict__ w_q, const float* __restrict__ b_q,
             const float* __restrict__ w_cq, const float* __restrict__ b_cq,
             float* __restrict__ out)
{
    __shared__ float bufA[64 * TS];   // phase1: c*w_cq tile | phase2/3: At[j][i]
    __shared__ float bufB[64 * TS];   // phase1/3: q tile    | between: S logits (stride SSS)
    __shared__ float qm_s[64];
    __shared__ float cw_s[64];
    __shared__ float qw_s[64];

    float* Ss = bufB;                 // alias, stride SSS (scalar access)
    float* At = bufA;                 // alias, stride TS

    const int t    = threadIdx.x;
    const int lane = t & 31;
    const int warp = t >> 5;
    const int tx   = t & 15;          // j-group (phase1) / d-group (phase3)
    const int ty   = t >> 4;          // i-group
    const int b    = blockIdx.x >> 3;
    const int i0   = (blockIdx.x & 7) * 64;

    if (t < 64) qm_s[t] = q_mask[b * QLn + t];

    // ---- row dots: cw[i] = c_i . w_c ; qw[j] = q_j . w_q ----
    {
        const float4* wc4 = (const float4*)w_c;
        const float4* wq4 = (const float4*)w_q;
        for (int task = warp; task < 128; task += 8) {
            const float4* row4;
            const float4* w4;
            if (task < 64) {
                row4 = (const float4*)(c + (size_t)(b * CLn + i0 + task) * Hdim);
                w4 = wc4;
            } else {
                row4 = (const float4*)(q + (size_t)(b * QLn + task - 64) * Hdim);
                w4 = wq4;
            }
            float s = 0.f;
            #pragma unroll
            for (int u = 0; u < 6; ++u) {
                float4 a = row4[lane + 32 * u];
                float4 w = w4[lane + 32 * u];
                s += a.x * w.x + a.y * w.y + a.z * w.z + a.w * w.w;
            }
            #pragma unroll
            for (int o = 16; o; o >>= 1) s += __shfl_xor_sync(0xffffffffu, s, o);
            if (lane == 0) { if (task < 64) cw_s[task] = s; else qw_s[task - 64] = s; }
        }
    }

    // ---- phase 1: S GEMM (K-chunks of 64), f32x2 pairing over K ----
    unsigned long long acc[4][4];
    #pragma unroll
    for (int r = 0; r < 4; ++r)
        #pragma unroll
        for (int rj = 0; rj < 4; ++rj) acc[r][rj] = 0ull;

    const float4* wcq4 = (const float4*)w_cq;
    for (int kc = 0; kc < 12; ++kc) {
        const float4* c4 = (const float4*)(c + (size_t)(b * CLn + i0) * Hdim + kc * 64);
        const float4* q4 = (const float4*)(q + (size_t)(b * QLn) * Hdim + kc * 64);
        __syncthreads();              // previous iteration done reading tiles
        #pragma unroll
        for (int u = 0; u < 4; ++u) {
            int idx = t + 256 * u;
            int row = idx >> 4, col = idx & 15;
            float4 v = c4[row * 192 + col];
            float4 w = wcq4[kc * 16 + col];
            v.x *= w.x; v.y *= w.y; v.z *= w.z; v.w *= w.w;
            *(float4*)(bufA + row * TS + col * 4) = v;
            // additive mod-16 swizzled store of q tile (conflict-free reads)
            *(float4*)(bufB + row * TS + (((col + (row >> 2)) & 15) << 2)) = q4[row * 192 + col];
        }
        __syncthreads();
        #pragma unroll 4
        for (int kk = 0; kk < 64; kk += 4) {
            const int gb = ((((kk >> 2) + tx) & 15) << 2);
            ulonglong2 A[4], Bv[4];
            #pragma unroll
            for (int r = 0; r < 4; ++r)
                A[r] = *(const ulonglong2*)(bufA + (ty * 4 + r) * TS + kk);
            #pragma unroll
            for (int rj = 0; rj < 4; ++rj)
                Bv[rj] = *(const ulonglong2*)(bufB + (tx * 4 + rj) * TS + gb);
            #pragma unroll
            for (int r = 0; r < 4; ++r)
                #pragma unroll
                for (int rj = 0; rj < 4; ++rj) {
                    fma2(acc[r][rj], A[r].x, Bv[rj].x);
                    fma2(acc[r][rj], A[r].y, Bv[rj].y);
                }
        }
    }
    __syncthreads();   // tiles dead; bufB becomes S logits

    // ---- finalize S logits into Ss (bufB) ----
    {
        const float bias = b_c[0] + b_q[0] + b_cq[0];
        #pragma unroll
        for (int r = 0; r < 4; ++r) {
            int i = ty * 4 + r;
            float base_i = cw_s[i] + bias;
            #pragma unroll
            for (int rj = 0; rj < 4; ++rj) {
                int j = tx * 4 + rj;
                float2 p = unpack2(acc[r][rj]);
                Ss[i * SSS + j] = p.x + p.y + base_i + qw_s[j];
            }
        }
    }
    __syncthreads();

    // ---- phase 2: softmax rows -> At[j][i] (bufA); masked row max -> g_m ----
    #pragma unroll
    for (int r8 = 0; r8 < 8; ++r8) {
        int i = warp * 8 + r8;
        float v0 = Ss[i * SSS + lane];
        float v1 = Ss[i * SSS + 32 + lane];
        float qm0 = qm_s[lane], qm1 = qm_s[32 + lane];
        float l0 = v0 * qm0 + (1.f - qm0) * NEGV;
        float l1 = v1 * qm1 + (1.f - qm1) * NEGV;
        float mx = fmaxf(l0, l1);
        #pragma unroll
        for (int o = 16; o; o >>= 1) mx = fmaxf(mx, __shfl_xor_sync(0xffffffffu, mx, o));
        float e0 = __expf(l0 - mx), e1 = __expf(l1 - mx);
        float s2 = e0 + e1;
        #pragma unroll
        for (int o = 16; o; o >>= 1) s2 += __shfl_xor_sync(0xffffffffu, s2, o);
        float inv = __fdividef(1.f, s2);
        At[lane * TS + i]        = e0 * inv;     // transposed store: At[j][i]
        At[(32 + lane) * TS + i] = e1 * inv;

        float cmv = c_mask[b * CLn + i0 + i];
        float f0 = v0 * cmv + (1.f - cmv) * NEGV;
        float f1 = v1 * cmv + (1.f - cmv) * NEGV;
        float mm = fmaxf(f0, f1);
        #pragma unroll
        for (int o = 16; o; o >>= 1) mm = fmaxf(mm, __shfl_xor_sync(0xffffffffu, mm, o));
        if (lane == 0) g_m[b * CLn + i0 + i] = mm;
    }

    // ---- phase 3: c2q = a @ q (d-chunks of 64); fused out chunks 0/1/2 ----
    for (int dc = 0; dc < 12; ++dc) {
        const int d0 = dc * 64;
        __syncthreads();              // At written / prior chunk reads done
        const float4* q4 = (const float4*)(q + (size_t)(b * QLn) * Hdim + d0);
        #pragma unroll
        for (int u = 0; u < 4; ++u) {
            int idx = t + 256 * u;
            int row = idx >> 4, col = idx & 15;
            *(float4*)(bufB + row * TS + col * 4) = q4[row * 192 + col];
        }
        __syncthreads();

        unsigned long long a3[4][2];
        #pragma unroll
        for (int r = 0; r < 4; ++r) { a3[r][0] = 0ull; a3[r][1] = 0ull; }

        #pragma unroll 4
        for (int j = 0; j < 64; ++j) {
            float4 av = *(const float4*)(At + j * TS + ty * 4);   // 4 rows' weights
            ulonglong2 qv = *(const ulonglong2*)(bufB + j * TS + tx * 4);
            unsigned long long ad;
            ad = pack2(av.x, av.x); fma2(a3[0][0], ad, qv.x); fma2(a3[0][1], ad, qv.y);
            ad = pack2(av.y, av.y); fma2(a3[1][0], ad, qv.x); fma2(a3[1][1], ad, qv.y);
            ad = pack2(av.z, av.z); fma2(a3[2][0], ad, qv.x); fma2(a3[2][1], ad, qv.y);
            ad = pack2(av.w, av.w); fma2(a3[3][0], ad, qv.x); fma2(a3[3][1], ad, qv.y);
        }

        #pragma unroll
        for (int r = 0; r < 4; ++r) {
            int i = ty * 4 + r;
            float4 cv = *(const float4*)(c + (size_t)(b * CLn + i0 + i) * Hdim + d0 + tx * 4);
            float2 p0 = unpack2(a3[r][0]);
            float2 p1 = unpack2(a3[r][1]);
            float4 t0 = make_float4(p0.x, p0.y, p1.x, p1.y);
            float* ob = out + (size_t)(b * CLn + i0 + i) * 3072 + d0 + tx * 4;
            *(float4*)(ob)        = cv;                                      // chunk 0: c
            *(float4*)(ob + 768)  = t0;                                      // chunk 1: c2q
            *(float4*)(ob + 1536) = make_float4(cv.x * t0.x, cv.y * t0.y,
                                                cv.z * t0.z, cv.w * t0.w);   // chunk 2
        }
    }
}

// =====================================================================
// K2a: b_att = softmax_i(g_m[b]) -> g_batt.  16 CTAs x 512 thr.
// =====================================================================
__global__ __launch_bounds__(512)
void k2a_softmax()
{
    __shared__ float red[16];
    const int b = blockIdx.x;
    const int t = threadIdx.x, lane = t & 31, warp = t >> 5;

    float m = g_m[b * CLn + t];
    float mx = m;
    #pragma unroll
    for (int o = 16; o; o >>= 1) mx = fmaxf(mx, __shfl_xor_sync(0xffffffffu, mx, o));
    if (lane == 0) red[warp] = mx;
    __syncthreads();
    float M = red[0];
    #pragma unroll
    for (int w = 1; w < 16; ++w) M = fmaxf(M, red[w]);
    float e = __expf(m - M);
    float s = e;
    #pragma unroll
    for (int o = 16; o; o >>= 1) s += __shfl_xor_sync(0xffffffffu, s, o);
    __syncthreads();
    if (lane == 0) red[warp] = s;
    __syncthreads();
    float S = 0.f;
    #pragma unroll
    for (int w = 0; w < 16; ++w) S += red[w];
    g_batt[b * CLn + t] = e * __fdividef(1.f, S);
}

// =====================================================================
// K2b: g_q2c[b,d] = sum_i b_att[i]*c[b,i,d].  grid (16,12), 256 thr.
// Each CTA: 64 columns, i-range split 4-way per column + smem reduce.
// Deterministic fixed-order reduction.
// =====================================================================
__global__ __launch_bounds__(256)
void k2b_q2c(const float* __restrict__ c)
{
    __shared__ float batt[CLn];
    __shared__ float part[4][64 + 1];
    const int b  = blockIdx.x;
    const int t  = threadIdx.x;
    const int col = blockIdx.y * 64 + (t & 63);
    const int ig  = t >> 6;                      // 0..3 -> i-range [ig*128, +128)

    batt[t]       = g_batt[b * CLn + t];
    batt[256 + t] = g_batt[b * CLn + 256 + t];
    __syncthreads();

    const float* cp = c + (size_t)b * CLn * Hdim + (size_t)(ig * 128) * Hdim + col;
    float acc = 0.f;
    #pragma unroll 8
    for (int i = 0; i < 128; ++i)
        acc += batt[ig * 128 + i] * cp[(size_t)i * Hdim];
    part[ig][t & 63] = acc;
    __syncthreads();

    if (t < 64)
        g_q2c[b * Hdim + blockIdx.y * 64 + t] =
            (part[0][t] + part[1][t]) + (part[2][t] + part[3][t]);
}

// =====================================================================
// K3: output chunk 3 = c * q2c (broadcast over i). Pure streaming.
// =====================================================================
__global__ __launch_bounds__(256)
void k3_mul(const float* __restrict__ c, float* __restrict__ out)
{
    const int f  = blockIdx.x * 256 + threadIdx.x;   // float4 index, 16*512*192 total
    const int d4 = f % 192;
    const int r  = f / 192;          // b*512 + i
    const int b  = r >> 9;
    float4 cv = ((const float4*)c)[f];
    float4 sv = ((const float4*)g_q2c)[b * 192 + d4];
    ((float4*)out)[(size_t)r * 768 + 576 + d4] =
        make_float4(cv.x * sv.x, cv.y * sv.y, cv.z * sv.z, cv.w * sv.w);
}

extern "C" void kernel_launch(void* const* d_in, const int* in_sizes, int n_in,
                              void* d_out, int out_size)
{
    const float* c      = (const float*)d_in[0];
    const float* q      = (const float*)d_in[1];
    const float* c_mask = (const float*)d_in[2];
    const float* q_mask = (const float*)d_in[3];
    const float* w_c    = (const float*)d_in[4];
    const float* b_c    = (const float*)d_in[5];
    const float* w_q    = (const float*)d_in[6];
    const float* b_q    = (const float*)d_in[7];
    const float* w_cq   = (const float*)d_in[8];
    const float* b_cq   = (const float*)d_in[9];
    float* out = (float*)d_out;

    k1_attn<<<128, 256>>>(c, q, c_mask, q_mask, w_c, b_c, w_q, b_q, w_cq, b_cq, out);
    k2a_softmax<<<16, 512>>>();
    k2b_q2c<<<dim3(16, 12), 256>>>(c);
    k3_mul<<<16 * 512 * 192 / 256, 256>>>(c, out);
}